// round 8
// baseline (speedup 1.0000x reference)
#include <cuda_runtime.h>
#include <stdint.h>

#define N_VOX        200000
#define N_COLS       5
#define N_CLUSTS     1024
#define PTS_PER      128
#define N_EDGES      8192
#define HALF_EDGES   (N_EDGES / 2)

typedef unsigned long long ull;

// Precomputed packed cluster points:
//  g1{x,y,z}[c*128+i] = (v, v)           duplicate-packed f32x2
//  g2{x,y,z}[c*64+k]  = (-v[2k], -v[2k+1]) negated pair-packed f32x2
__device__ ull g1x[N_CLUSTS * PTS_PER];
__device__ ull g1y[N_CLUSTS * PTS_PER];
__device__ ull g1z[N_CLUSTS * PTS_PER];
__device__ ull g2x[N_CLUSTS * PTS_PER / 2];
__device__ ull g2y[N_CLUSTS * PTS_PER / 2];
__device__ ull g2z[N_CLUSTS * PTS_PER / 2];

// ---- packed f32x2 helpers (sm_103a FFMA2 path, PTX-only) ----
__device__ __forceinline__ ull pack2(float lo, float hi) {
    ull r; asm("mov.b64 %0, {%1,%2};" : "=l"(r) : "f"(lo), "f"(hi)); return r;
}
__device__ __forceinline__ void unpack2(ull v, float& lo, float& hi) {
    asm("mov.b64 {%0,%1}, %2;" : "=f"(lo), "=f"(hi) : "l"(v));
}
__device__ __forceinline__ ull add2(ull a, ull b) {
    ull r; asm("add.rn.f32x2 %0, %1, %2;" : "=l"(r) : "l"(a), "l"(b)); return r;
}
__device__ __forceinline__ ull mul2(ull a, ull b) {
    ull r; asm("mul.rn.f32x2 %0, %1, %2;" : "=l"(r) : "l"(a), "l"(b)); return r;
}
__device__ __forceinline__ ull fma2(ull a, ull b, ull c) {
    ull r; asm("fma.rn.f32x2 %0, %1, %2, %3;" : "=l"(r) : "l"(a), "l"(b), "l"(c)); return r;
}

// -------------------------------------------------------------------------
// Kernel 1: gather + pre-pack. One thread per cluster point.
// -------------------------------------------------------------------------
__global__ void gather_pts_kernel(const float* __restrict__ data,
                                  const int* __restrict__ clusts) {
    int i = blockIdx.x * blockDim.x + threadIdx.x;
    if (i >= N_CLUSTS * PTS_PER) return;
    int idx = clusts[i];
    const float* p = data + (size_t)idx * N_COLS + 1;
    float x = p[0], y = p[1], z = p[2];

    g1x[i] = pack2(x, x);
    g1y[i] = pack2(y, y);
    g1z[i] = pack2(z, z);

    // Negated pair-pack: lanes (2k, 2k+1). Pairs never cross a warp boundary.
    float mx = -x, my = -y, mz = -z;
    float ox = __shfl_down_sync(0xFFFFFFFFu, mx, 1);
    float oy = __shfl_down_sync(0xFFFFFFFFu, my, 1);
    float oz = __shfl_down_sync(0xFFFFFFFFu, mz, 1);
    if ((i & 1) == 0) {
        int k = i >> 1;
        g2x[k] = pack2(mx, ox);
        g2y[k] = pack2(my, oy);
        g2z[k] = pack2(mz, oz);
    }
}

// -------------------------------------------------------------------------
// Kernel 2: one CTA (128 threads) per TWO edges (e, e + 4096).
// Thread (ti, tj): ti = t>>4 owns i1 rows [16*ti, 16*ti+16);
//                  tj = t&15 owns i2 packs k = tj + 16*b (b=0..3).
// 128 pairs per thread per edge. s1 x/y packs merged into ulonglong2 (LDS.128).
// -------------------------------------------------------------------------
__global__ __launch_bounds__(128, 8)
void edge_feats_kernel(const int* __restrict__ edge_index,
                       float* __restrict__ out) {
    __shared__ ulonglong2 s1xy[2][PTS_PER];
    __shared__ ull        s1z [2][PTS_PER];
    __shared__ ull s2x[2][64], s2y[2][64], s2z[2][64];
    __shared__ ull s_best[2];

    const int t = threadIdx.x;
    const int e0 = blockIdx.x;              // first edge
    const int e1 = blockIdx.x + HALF_EDGES; // second edge

    const int c1a = edge_index[e0];
    const int c1b = edge_index[e1];
    const int c2a = edge_index[N_EDGES + e0];
    const int c2b = edge_index[N_EDGES + e1];

    if (t == 0) { s_best[0] = ~0ull; s_best[1] = ~0ull; }

    // Prologue: pure coalesced LDG.64 -> STS (no packing math).
    {
        int ia = c1a * PTS_PER + t;
        int ib = c1b * PTS_PER + t;
        s1xy[0][t] = make_ulonglong2(g1x[ia], g1y[ia]);
        s1z [0][t] = g1z[ia];
        s1xy[1][t] = make_ulonglong2(g1x[ib], g1y[ib]);
        s1z [1][t] = g1z[ib];
        if (t < 64) {
            int ka = c2a * 64 + t;
            int kb = c2b * 64 + t;
            s2x[0][t] = g2x[ka]; s2y[0][t] = g2y[ka]; s2z[0][t] = g2z[ka];
            s2x[1][t] = g2x[kb]; s2y[1][t] = g2y[kb]; s2z[1][t] = g2z[kb];
        }
    }
    __syncthreads();

    const int ti = t >> 4;
    const int tj = t & 15;
    const int i1base = ti * 16;

#pragma unroll
    for (int ed = 0; ed < 2; ed++) {
        // Hoist this edge's 4 negated-v2 packs (conflict-free LDS.64).
        ull vx[4], vy[4], vz[4];
#pragma unroll
        for (int b = 0; b < 4; b++) {
            vx[b] = s2x[ed][tj + 16 * b];
            vy[b] = s2y[ed][tj + 16 * b];
            vz[b] = s2z[ed][tj + 16 * b];
        }

        float bd = __int_as_float(0x7F800000);   // +inf
        int besta = 0;

        // ---- hot loop: 16 rows; packed distances + scalar min tree ----
#pragma unroll
        for (int a = 0; a < 16; a++) {
            ulonglong2 pxy = s1xy[ed][i1base + a];
            ull pz = s1z[ed][i1base + a];

            float h[8];
#pragma unroll
            for (int b = 0; b < 4; b++) {
                ull dx = add2(pxy.x, vx[b]);
                ull dy = add2(pxy.y, vy[b]);
                ull dz = add2(pz,    vz[b]);
                ull d2 = fma2(dz, dz, fma2(dy, dy, mul2(dx, dx)));
                unpack2(d2, h[2 * b], h[2 * b + 1]);
            }

            float m01 = fminf(h[0], h[1]);
            float m23 = fminf(h[2], h[3]);
            float m45 = fminf(h[4], h[5]);
            float m67 = fminf(h[6], h[7]);
            float m = fminf(fminf(m01, m23), fminf(m45, m67));

            // Last strict improvement == first row attaining the final min.
            bool imp = (m < bd);
            bd = imp ? m : bd;
            besta = imp ? a : besta;
        }

        // ---- one-shot index recovery: recompute row `besta` (identical math) ----
        {
            ulonglong2 pxy = s1xy[ed][i1base + besta];
            ull pz = s1z[ed][i1base + besta];

            float h[8];
#pragma unroll
            for (int b = 0; b < 4; b++) {
                ull dx = add2(pxy.x, vx[b]);
                ull dy = add2(pxy.y, vy[b]);
                ull dz = add2(pz,    vz[b]);
                ull d2 = fma2(dz, dz, fma2(dy, dy, mul2(dx, dx)));
                unpack2(d2, h[2 * b], h[2 * b + 1]);
            }

            float cur = __int_as_float(0x7F800000);
            int bidx = 0;
            const int rowbase = (i1base + besta) * PTS_PER + 2 * tj;
#pragma unroll
            for (int q = 0; q < 8; q++) {
                int flat = rowbase + 32 * (q >> 1) + (q & 1);
                if (h[q] < cur) { cur = h[q]; bidx = flat; }   // ascending flat, strict <
            }

            // Pack (d2, flat): uint64 min == lexicographic min (d2 >= 0).
            ull key = ((ull)__float_as_uint(cur) << 32) | (unsigned int)bidx;

#pragma unroll
            for (int off = 16; off > 0; off >>= 1) {
                ull o = __shfl_down_sync(0xFFFFFFFFu, key, off);
                key = (o < key) ? o : key;
            }
            if ((t & 31) == 0) atomicMin(&s_best[ed], key);
        }
    }
    __syncthreads();

    // Two parallel writers in different warps.
    if (t == 0 || t == 64) {
        const int ed = (t == 0) ? 0 : 1;
        const int e  = (ed == 0) ? e0 : e1;

        ull k = s_best[ed];
        int f  = (int)(k & 0xFFFFFFFFu);
        int w1 = f >> 7;
        int w2 = f & 127;

        float v1x, v1y, v1z, tmp;
        ulonglong2 pxy = s1xy[ed][w1];
        unpack2(pxy.x, v1x, tmp);
        unpack2(pxy.y, v1y, tmp);
        unpack2(s1z[ed][w1], v1z, tmp);

        int kk = w2 >> 1, half = w2 & 1;
        float lox, hix, loy, hiy, loz, hiz;
        unpack2(s2x[ed][kk], lox, hix);
        unpack2(s2y[ed][kk], loy, hiy);
        unpack2(s2z[ed][kk], loz, hiz);
        float v2x = -(half ? hix : lox);
        float v2y = -(half ? hiy : loy);
        float v2z = -(half ? hiz : loz);

        float dx = v1x - v2x;
        float dy = v1y - v2y;
        float dz = v1z - v2z;
        float lend = sqrtf(fmaf(dz, dz, fmaf(dy, dy, dx * dx)));
        float nx, ny, nz;
        if (lend > 0.0f) {
            nx = dx / lend; ny = dy / lend; nz = dz / lend;
        } else {
            nx = dx; ny = dy; nz = dz;
        }

        float B[9];
        B[0] = nx * nx; B[1] = nx * ny; B[2] = nx * nz;
        B[3] = ny * nx; B[4] = ny * ny; B[5] = ny * nz;
        B[6] = nz * nx; B[7] = nz * ny; B[8] = nz * nz;

        float* o1 = out + (size_t)e * 38;
        float* o2 = o1 + 19;

        o1[0] = v1x; o1[1] = v1y; o1[2] = v1z;
        o1[3] = v2x; o1[4] = v2y; o1[5] = v2z;
        o1[6] = nx;  o1[7] = ny;  o1[8] = nz;
        o1[9] = lend;
#pragma unroll
        for (int q = 0; q < 9; q++) o1[10 + q] = B[q];

        o2[0] = v2x; o2[1] = v2y; o2[2] = v2z;
        o2[3] = v1x; o2[4] = v1y; o2[5] = v1z;
        o2[6] = -nx; o2[7] = -ny; o2[8] = -nz;
        o2[9] = lend;
#pragma unroll
        for (int q = 0; q < 9; q++) o2[10 + q] = B[q];
    }
}

// -------------------------------------------------------------------------
extern "C" void kernel_launch(void* const* d_in, const int* in_sizes, int n_in,
                              void* d_out, int out_size) {
    const float* data       = (const float*)d_in[0];   // [200000, 5] f32
    const int*   clusts     = (const int*)d_in[1];     // [1024, 128] i32
    const int*   edge_index = (const int*)d_in[2];     // [2, 8192] i32
    float*       out        = (float*)d_out;           // [16384, 19] f32

    gather_pts_kernel<<<(N_CLUSTS * PTS_PER + 255) / 256, 256>>>(data, clusts);
    edge_feats_kernel<<<HALF_EDGES, 128>>>(edge_index, out);
}